// round 2
// baseline (speedup 1.0000x reference)
#include <cuda_runtime.h>
#include <cuda_bf16.h>
#include <mma.h>

using namespace nvcuda;

// Problem constants (fixed by setup_inputs)
#define BB 8
#define HH 64
#define WW 64
#define TT 4096          // HH*WW
#define CC 768
#define MM (BB * TT)     // 32768
#define ELEMS (BB * TT * CC)

// Shift table (24 groups of 32 channels)
__constant__ int c_dy[24] = {0, 0, 1, -1, 1, -1, 1, -1, 0, 0, 2, -2, 2, -2, 2, -2, 2, 1, 2, 1, -2, -1, -2, -1};
__constant__ int c_dx[24] = {1, -1, 0, 0, 1, -1, -1, 1, 2, -2, 0, 0, 2, -2, -2, 2, 1, 2, -1, -2, 1, 2, -1, -2};

// Scratch buffers (no cudaMalloc allowed)
__device__ float g_xs[ELEMS];
__device__ float g_k[ELEMS];
__device__ float g_v[ELEMS];
__device__ float g_sr[ELEMS];
__device__ float g_v1[ELEMS];
__device__ float g_vf[ELEMS];

// ---------------------------------------------------------------------------
// 1) shift (mul_shift) + zigzag reorder, fused gather.
//    xs[b, t, c] = shifted_x[b, c, order[t]], order[t] closed-form.
// ---------------------------------------------------------------------------
__global__ void shift_gather_kernel(const float* __restrict__ x, float* __restrict__ xs)
{
    int gid = blockIdx.x * blockDim.x + threadIdx.x;       // over B*T*(C/4)
    const int CV = CC / 4;
    if (gid >= BB * TT * CV) return;
    int cv = gid % CV;
    int bt = gid / CV;
    int t  = bt % TT;
    int b  = bt / TT;
    int c  = cv * 4;

    int r   = t >> 6;
    int j   = t & 63;
    int col = (r & 1) ? (63 - j) : j;                      // order[t] = (r, col)

    int g   = c >> 5;
    int srow = r - c_dy[g];
    int scol = col - c_dx[g];

    float4 val = make_float4(0.f, 0.f, 0.f, 0.f);
    if ((unsigned)srow < (unsigned)HH && (unsigned)scol < (unsigned)WW) {
        val = *(const float4*)&x[((size_t)b * TT + srow * WW + scol) * CC + c];
    }
    *(float4*)&xs[((size_t)b * TT + t) * CC + c] = val;
}

// ---------------------------------------------------------------------------
// 2) tf32 tensor-core GEMM:  C[m,n] = sum_k A[m,k] * W[n,k]
//    BM=128, BN=64, BK=32, 256 threads (8 warps, 4x2), warp tile 32x32.
//    EPI: 0 = none, 1 = sigmoid.  FUSEA: A := A .* A2 (elementwise) on load.
// ---------------------------------------------------------------------------
template <int EPI, bool FUSEA>
__global__ __launch_bounds__(256)
void gemm_tf32_kernel(const float* __restrict__ A, const float* __restrict__ A2,
                      const float* __restrict__ Wt, float* __restrict__ Co)
{
    constexpr int BM = 128, BN = 64, BK = 32, PAD = 4;
    constexpr int LD = BK + PAD;                            // 36 floats (16B aligned rows)
    constexpr int K = CC, N = CC;

    __shared__ float As[BM][LD];
    __shared__ float Bs[BN][LD];

    const int m0 = blockIdx.y * BM;
    const int n0 = blockIdx.x * BN;
    const int warp = threadIdx.x >> 5;
    const int wm = warp >> 1;                               // 0..3
    const int wn = warp & 1;                                // 0..1

    wmma::fragment<wmma::accumulator, 16, 16, 8, float> cf[2][2];
#pragma unroll
    for (int i = 0; i < 2; i++)
#pragma unroll
        for (int jn = 0; jn < 2; jn++)
            wmma::fill_fragment(cf[i][jn], 0.f);

    for (int k0 = 0; k0 < K; k0 += BK) {
        // load A tile: 128x32 floats = 1024 float4, 4 per thread
#pragma unroll
        for (int i = 0; i < 4; i++) {
            int idx = threadIdx.x + i * 256;
            int row = idx >> 3;
            int cv  = idx & 7;
            float4 v = *(const float4*)&A[(size_t)(m0 + row) * K + k0 + cv * 4];
            if (FUSEA) {
                float4 v2 = *(const float4*)&A2[(size_t)(m0 + row) * K + k0 + cv * 4];
                v.x *= v2.x; v.y *= v2.y; v.z *= v2.z; v.w *= v2.w;
            }
            *(float4*)&As[row][cv * 4] = v;
        }
        // load B tile (rows of W): 64x32 = 512 float4, 2 per thread
#pragma unroll
        for (int i = 0; i < 2; i++) {
            int idx = threadIdx.x + i * 256;
            int row = idx >> 3;
            int cv  = idx & 7;
            *(float4*)&Bs[row][cv * 4] = *(const float4*)&Wt[(size_t)(n0 + row) * K + k0 + cv * 4];
        }
        __syncthreads();

#pragma unroll
        for (int kk = 0; kk < BK; kk += 8) {
            wmma::fragment<wmma::matrix_a, 16, 16, 8, wmma::precision::tf32, wmma::row_major> af[2];
            wmma::fragment<wmma::matrix_b, 16, 16, 8, wmma::precision::tf32, wmma::col_major> bf[2];
#pragma unroll
            for (int i = 0; i < 2; i++) {
                wmma::load_matrix_sync(af[i], &As[wm * 32 + i * 16][kk], LD);
#pragma unroll
                for (int e = 0; e < af[i].num_elements; e++)
                    af[i].x[e] = wmma::__float_to_tf32(af[i].x[e]);
            }
#pragma unroll
            for (int jn = 0; jn < 2; jn++) {
                wmma::load_matrix_sync(bf[jn], &Bs[wn * 32 + jn * 16][kk], LD);
#pragma unroll
                for (int e = 0; e < bf[jn].num_elements; e++)
                    bf[jn].x[e] = wmma::__float_to_tf32(bf[jn].x[e]);
            }
#pragma unroll
            for (int i = 0; i < 2; i++)
#pragma unroll
                for (int jn = 0; jn < 2; jn++)
                    wmma::mma_sync(cf[i][jn], af[i], bf[jn], cf[i][jn]);
        }
        __syncthreads();
    }

#pragma unroll
    for (int i = 0; i < 2; i++) {
#pragma unroll
        for (int jn = 0; jn < 2; jn++) {
            if (EPI == 1) {
#pragma unroll
                for (int e = 0; e < cf[i][jn].num_elements; e++)
                    cf[i][jn].x[e] = 1.f / (1.f + __expf(-cf[i][jn].x[e]));
            }
            wmma::store_matrix_sync(
                &Co[(size_t)(m0 + wm * 32 + i * 16) * N + n0 + wn * 32 + jn * 16],
                cf[i][jn], N, wmma::mem_row_major);
        }
    }
}

// ---------------------------------------------------------------------------
// 3) WKV recurrence. One thread per (b, c) lane; T sequential steps.
//    PASS 0: identity order. PASS 1: read & write at order[s] (order is an
//    involution, so writing at order[s] directly produces v2[inv[t]] in t-space).
// ---------------------------------------------------------------------------
template <int PASS>
__global__ __launch_bounds__(128)
void wkv_kernel(const float* __restrict__ kk, const float* __restrict__ vv,
                const float* __restrict__ decay, const float* __restrict__ first,
                float* __restrict__ yo)
{
    int gid = blockIdx.x * blockDim.x + threadIdx.x;
    if (gid >= BB * CC) return;
    int b = gid / CC;
    int c = gid % CC;

    const float invT = 1.f / (float)TT;
    const float w = decay[PASS * CC + c] * invT;
    const float u = first[PASS * CC + c] * invT;

    const size_t base = (size_t)b * TT * CC + c;

    float p = 0.f, q = 0.f, o = -1e38f;

#pragma unroll 4
    for (int t = 0; t < TT; t++) {
        int pidx;
        if (PASS == 0) {
            pidx = t;
        } else {
            int r = t >> 6, j = t & 63;
            pidx = (r << 6) + ((r & 1) ? (63 - j) : j);
        }
        size_t idx = base + (size_t)pidx * CC;
        float kt = kk[idx];
        float vt = vv[idx];

        float uk = u + kt;
        float no = fmaxf(o, uk);
        float Ac = __expf(o - no);
        float Bc = __expf(uk - no);
        float y  = __fdividef(Ac * p + Bc * vt, Ac * q + Bc);
        yo[idx] = y;

        float wo  = w + o;
        float no2 = fmaxf(wo, kt);
        float A2  = __expf(wo - no2);
        float B2  = __expf(kt - no2);
        p = A2 * p + B2 * vt;
        q = A2 * q + B2;
        o = no2;
    }
}

// ---------------------------------------------------------------------------
// Launch
// ---------------------------------------------------------------------------
extern "C" void kernel_launch(void* const* d_in, const int* in_sizes, int n_in,
                              void* d_out, int out_size)
{
    const float* x    = (const float*)d_in[0];
    const float* kw   = (const float*)d_in[1];
    const float* vw   = (const float*)d_in[2];
    const float* rw   = (const float*)d_in[3];
    const float* ow   = (const float*)d_in[4];
    const float* sdec = (const float*)d_in[5];
    const float* sfst = (const float*)d_in[6];
    float* out        = (float*)d_out;

    float *xs, *k, *v, *sr, *v1, *vf;
    cudaGetSymbolAddress((void**)&xs, g_xs);
    cudaGetSymbolAddress((void**)&k,  g_k);
    cudaGetSymbolAddress((void**)&v,  g_v);
    cudaGetSymbolAddress((void**)&sr, g_sr);
    cudaGetSymbolAddress((void**)&v1, g_v1);
    cudaGetSymbolAddress((void**)&vf, g_vf);

    // 1) shift + zigzag gather
    {
        int total = BB * TT * (CC / 4);
        shift_gather_kernel<<<(total + 255) / 256, 256>>>(x, xs);
    }

    // 2) k, v, sr GEMMs (sigmoid fused into sr)
    {
        dim3 grid(CC / 64, MM / 128);
        gemm_tf32_kernel<0, false><<<grid, 256>>>(xs, nullptr, kw, k);
        gemm_tf32_kernel<0, false><<<grid, 256>>>(xs, nullptr, vw, v);
        gemm_tf32_kernel<1, false><<<grid, 256>>>(xs, nullptr, rw, sr);
    }

    // 3) WKV pass 1 (t order), pass 2 (order[s] permuted, writes back in t-space)
    {
        int lanes = BB * CC;
        wkv_kernel<0><<<(lanes + 127) / 128, 128>>>(k, v,  sdec, sfst, v1);
        wkv_kernel<1><<<(lanes + 127) / 128, 128>>>(k, v1, sdec, sfst, vf);
    }

    // 4) out = (sr .* vf) @ ow^T   (elementwise product fused into A load)
    {
        dim3 grid(CC / 64, MM / 128);
        gemm_tf32_kernel<0, true><<<grid, 256>>>(sr, vf, ow, out);
    }
}

// round 4
// speedup vs baseline: 1.3670x; 1.3670x over previous
#include <cuda_runtime.h>
#include <cuda_bf16.h>
#include <mma.h>
#include <cstdint>

using namespace nvcuda;

// Problem constants (fixed by setup_inputs)
#define BB 8
#define HH 64
#define WW 64
#define TT 4096          // HH*WW
#define CC 768
#define MM (BB * TT)     // 32768
#define ELEMS (BB * TT * CC)
#define SEG 64
#define NSEG 64
#define LANES (BB * CC)  // 6144

// Shift table (24 groups of 32 channels)
__constant__ int c_dy[24] = {0, 0, 1, -1, 1, -1, 1, -1, 0, 0, 2, -2, 2, -2, 2, -2, 2, 1, 2, 1, -2, -1, -2, -1};
__constant__ int c_dx[24] = {1, -1, 0, 0, 1, -1, -1, 1, 2, -2, 0, 0, 2, -2, -2, 2, 1, 2, -1, -2, 1, 2, -1, -2};

// Scratch buffers (no cudaMalloc allowed)
__device__ float g_xs[ELEMS];
__device__ float g_k[ELEMS];
__device__ float g_v[ELEMS];
__device__ float g_sr[ELEMS];
__device__ float g_v1[ELEMS];
__device__ float g_vf[ELEMS];
// WKV segment summaries + carry-in states
__device__ float g_sp[NSEG][LANES];
__device__ float g_sq[NSEG][LANES];
__device__ float g_so[NSEG][LANES];
__device__ float g_cp[NSEG][LANES];
__device__ float g_cq[NSEG][LANES];
__device__ float g_co[NSEG][LANES];

__device__ __forceinline__ int zig(int t) {
    int r = t >> 6, j = t & 63;
    return (r << 6) + ((r & 1) ? (63 - j) : j);
}

// ---------------------------------------------------------------------------
// 1) shift (mul_shift) + zigzag reorder, fused gather.
// ---------------------------------------------------------------------------
__global__ void shift_gather_kernel(const float* __restrict__ x, float* __restrict__ xs)
{
    int gid = blockIdx.x * blockDim.x + threadIdx.x;       // over B*T*(C/4)
    const int CV = CC / 4;
    if (gid >= BB * TT * CV) return;
    int cv = gid % CV;
    int bt = gid / CV;
    int t  = bt % TT;
    int b  = bt / TT;
    int c  = cv * 4;

    int r   = t >> 6;
    int j   = t & 63;
    int col = (r & 1) ? (63 - j) : j;                      // order[t] = (r, col)

    int g   = c >> 5;
    int srow = r - c_dy[g];
    int scol = col - c_dx[g];

    float4 val = make_float4(0.f, 0.f, 0.f, 0.f);
    if ((unsigned)srow < (unsigned)HH && (unsigned)scol < (unsigned)WW) {
        val = *(const float4*)&x[((size_t)b * TT + srow * WW + scol) * CC + c];
    }
    *(float4*)&xs[((size_t)b * TT + t) * CC + c] = val;
}

// ---------------------------------------------------------------------------
// elementwise: o = a .* b  (vectorized)
// ---------------------------------------------------------------------------
__global__ void ewmul_kernel(const float* __restrict__ a, const float* __restrict__ b,
                             float* __restrict__ o)
{
    int gid = blockIdx.x * blockDim.x + threadIdx.x;
    if (gid >= ELEMS / 4) return;
    float4 va = ((const float4*)a)[gid];
    float4 vb = ((const float4*)b)[gid];
    va.x *= vb.x; va.y *= vb.y; va.z *= vb.z; va.w *= vb.w;
    ((float4*)o)[gid] = va;
}

// ---------------------------------------------------------------------------
// cp.async helpers
// ---------------------------------------------------------------------------
__device__ __forceinline__ void cp_async16(void* smem, const void* gmem) {
    unsigned int s = (unsigned int)__cvta_generic_to_shared(smem);
    asm volatile("cp.async.cg.shared.global [%0], [%1], 16;\n" :: "r"(s), "l"(gmem));
}
__device__ __forceinline__ void cp_commit() { asm volatile("cp.async.commit_group;\n" ::: "memory"); }
template<int N> __device__ __forceinline__ void cp_wait() { asm volatile("cp.async.wait_group %0;\n" :: "n"(N) : "memory"); }

// ---------------------------------------------------------------------------
// 2) tf32 tensor-core GEMM with cp.async double buffering.
//    C[m,n] = sum_k A[m,k] * W[n,k].  BM=128 BN=128 BK=16, 256 thr, 8 warps
//    (4x2), warp tile 32x64.  EPI: 0 none, 1 sigmoid.
// ---------------------------------------------------------------------------
template <int EPI>
__global__ __launch_bounds__(256)
void gemm_tf32_kernel(const float* __restrict__ A, const float* __restrict__ Wt,
                      float* __restrict__ Co)
{
    constexpr int BM = 128, BN = 128, BK = 16, PAD = 4;
    constexpr int LD = BK + PAD;                            // 20 floats
    constexpr int K = CC, N = CC;

    __shared__ float As[2][BM][LD];
    __shared__ float Bs[2][BN][LD];

    const int m0 = blockIdx.y * BM;
    const int n0 = blockIdx.x * BN;
    const int tid = threadIdx.x;
    const int warp = tid >> 5;
    const int wm = warp >> 1;                               // 0..3 -> 32-row slab
    const int wn = warp & 1;                                // 0..1 -> 64-col slab

    wmma::fragment<wmma::accumulator, 16, 16, 8, float> cf[2][4];
#pragma unroll
    for (int i = 0; i < 2; i++)
#pragma unroll
        for (int jn = 0; jn < 4; jn++)
            wmma::fill_fragment(cf[i][jn], 0.f);

    // loader: each thread moves 2x16B for A and 2x16B for B per stage
    auto issue_loads = [&](int st, int k0) {
#pragma unroll
        for (int i = 0; i < 2; i++) {
            int idx = tid + i * 256;                        // 0..511
            int row = idx >> 2;                             // 0..127
            int c4  = idx & 3;                              // 0..3
            cp_async16(&As[st][row][c4 * 4], &A[(size_t)(m0 + row) * K + k0 + c4 * 4]);
        }
#pragma unroll
        for (int i = 0; i < 2; i++) {
            int idx = tid + i * 256;
            int row = idx >> 2;
            int c4  = idx & 3;
            cp_async16(&Bs[st][row][c4 * 4], &Wt[(size_t)(n0 + row) * K + k0 + c4 * 4]);
        }
    };

    // prologue: stage 0
    issue_loads(0, 0);
    cp_commit();

    int st = 0;
    for (int k0 = 0; k0 < K; k0 += BK, st ^= 1) {
        // prefetch next stage (or empty group to keep counts aligned)
        if (k0 + BK < K) issue_loads(st ^ 1, k0 + BK);
        cp_commit();
        cp_wait<1>();            // stage 'st' resident
        __syncthreads();

#pragma unroll
        for (int kk = 0; kk < BK; kk += 8) {
            wmma::fragment<wmma::matrix_a, 16, 16, 8, wmma::precision::tf32, wmma::row_major> af[2];
            wmma::fragment<wmma::matrix_b, 16, 16, 8, wmma::precision::tf32, wmma::col_major> bf[4];
#pragma unroll
            for (int i = 0; i < 2; i++) {
                wmma::load_matrix_sync(af[i], &As[st][wm * 32 + i * 16][kk], LD);
#pragma unroll
                for (int e = 0; e < af[i].num_elements; e++)
                    af[i].x[e] = wmma::__float_to_tf32(af[i].x[e]);
            }
#pragma unroll
            for (int jn = 0; jn < 4; jn++) {
                wmma::load_matrix_sync(bf[jn], &Bs[st][wn * 64 + jn * 16][kk], LD);
#pragma unroll
                for (int e = 0; e < bf[jn].num_elements; e++)
                    bf[jn].x[e] = wmma::__float_to_tf32(bf[jn].x[e]);
            }
#pragma unroll
            for (int i = 0; i < 2; i++)
#pragma unroll
                for (int jn = 0; jn < 4; jn++)
                    wmma::mma_sync(cf[i][jn], af[i], bf[jn], cf[i][jn]);
        }
        __syncthreads();         // protect stage about to be overwritten
    }

#pragma unroll
    for (int i = 0; i < 2; i++) {
#pragma unroll
        for (int jn = 0; jn < 4; jn++) {
            if (EPI == 1) {
#pragma unroll
                for (int e = 0; e < cf[i][jn].num_elements; e++)
                    cf[i][jn].x[e] = 1.f / (1.f + __expf(-cf[i][jn].x[e]));
            }
            wmma::store_matrix_sync(
                &Co[(size_t)(m0 + wm * 32 + i * 16) * N + n0 + wn * 64 + jn * 16],
                cf[i][jn], N, wmma::mem_row_major);
        }
    }
}

// ---------------------------------------------------------------------------
// 3) WKV, chunked parallel scan. State (p,q,o) composes associatively.
//    Phase A: per-segment summaries (parallel over LANES x NSEG).
//    Phase B: sequential combine over 64 segments (parallel over LANES),
//             storing the carry-in (state entering each segment).
//    Phase C: replay each segment from its carry-in, emitting y.
// ---------------------------------------------------------------------------
template <int PASS>
__global__ __launch_bounds__(128)
void wkv_summary_kernel(const float* __restrict__ kk, const float* __restrict__ vv,
                        const float* __restrict__ decay)
{
    int lane = blockIdx.x * 128 + threadIdx.x;              // 0..LANES-1
    int seg  = blockIdx.y;
    int b = lane / CC;
    int c = lane % CC;
    const float w = decay[PASS * CC + c] * (1.f / (float)TT);
    const size_t base = (size_t)b * TT * CC + c;

    float p = 0.f, q = 0.f, o = -1e38f;
#pragma unroll 8
    for (int t = 0; t < SEG; t++) {
        int tt = seg * SEG + t;
        int pidx = (PASS == 0) ? tt : zig(tt);
        size_t idx = base + (size_t)pidx * CC;
        float kt = kk[idx];
        float vt = vv[idx];
        float wo  = w + o;
        float no2 = fmaxf(wo, kt);
        float A2  = __expf(wo - no2);
        float B2  = __expf(kt - no2);
        p = A2 * p + B2 * vt;
        q = A2 * q + B2;
        o = no2;
    }
    g_sp[seg][lane] = p;
    g_sq[seg][lane] = q;
    g_so[seg][lane] = o;
}

template <int PASS>
__global__ __launch_bounds__(128)
void wkv_scan_kernel(const float* __restrict__ decay)
{
    int lane = blockIdx.x * 128 + threadIdx.x;
    if (lane >= LANES) return;
    int c = lane % CC;
    const float w  = decay[PASS * CC + c] * (1.f / (float)TT);
    const float wL = w * (float)SEG;

    float p = 0.f, q = 0.f, o = -1e38f;
#pragma unroll
    for (int seg = 0; seg < NSEG; seg++) {
        g_cp[seg][lane] = p;
        g_cq[seg][lane] = q;
        g_co[seg][lane] = o;
        float o1 = o + wL;
        float p2 = g_sp[seg][lane];
        float q2 = g_sq[seg][lane];
        float o2 = g_so[seg][lane];
        float no = fmaxf(o1, o2);
        float e1 = __expf(o1 - no);
        float e2 = __expf(o2 - no);
        p = e1 * p + e2 * p2;
        q = e1 * q + e2 * q2;
        o = no;
    }
}

template <int PASS>
__global__ __launch_bounds__(128)
void wkv_replay_kernel(const float* __restrict__ kk, const float* __restrict__ vv,
                       const float* __restrict__ decay, const float* __restrict__ first,
                       float* __restrict__ yo)
{
    int lane = blockIdx.x * 128 + threadIdx.x;
    int seg  = blockIdx.y;
    int b = lane / CC;
    int c = lane % CC;
    const float invT = 1.f / (float)TT;
    const float w = decay[PASS * CC + c] * invT;
    const float u = first[PASS * CC + c] * invT;
    const size_t base = (size_t)b * TT * CC + c;

    float p = g_cp[seg][lane];
    float q = g_cq[seg][lane];
    float o = g_co[seg][lane];

#pragma unroll 8
    for (int t = 0; t < SEG; t++) {
        int tt = seg * SEG + t;
        int pidx = (PASS == 0) ? tt : zig(tt);
        size_t idx = base + (size_t)pidx * CC;
        float kt = kk[idx];
        float vt = vv[idx];

        float uk = u + kt;
        float no = fmaxf(o, uk);
        float Ac = __expf(o - no);
        float Bc = __expf(uk - no);
        float y  = __fdividef(Ac * p + Bc * vt, Ac * q + Bc);
        yo[idx] = y;

        float wo  = w + o;
        float no2 = fmaxf(wo, kt);
        float A2  = __expf(wo - no2);
        float B2  = __expf(kt - no2);
        p = A2 * p + B2 * vt;
        q = A2 * q + B2;
        o = no2;
    }
}

// ---------------------------------------------------------------------------
// Launch
// ---------------------------------------------------------------------------
extern "C" void kernel_launch(void* const* d_in, const int* in_sizes, int n_in,
                              void* d_out, int out_size)
{
    const float* x    = (const float*)d_in[0];
    const float* kw   = (const float*)d_in[1];
    const float* vw   = (const float*)d_in[2];
    const float* rw   = (const float*)d_in[3];
    const float* ow   = (const float*)d_in[4];
    const float* sdec = (const float*)d_in[5];
    const float* sfst = (const float*)d_in[6];
    float* out        = (float*)d_out;

    float *xs, *k, *v, *sr, *v1, *vf;
    cudaGetSymbolAddress((void**)&xs, g_xs);
    cudaGetSymbolAddress((void**)&k,  g_k);
    cudaGetSymbolAddress((void**)&v,  g_v);
    cudaGetSymbolAddress((void**)&sr, g_sr);
    cudaGetSymbolAddress((void**)&v1, g_v1);
    cudaGetSymbolAddress((void**)&vf, g_vf);

    // 1) shift + zigzag gather
    {
        int total = BB * TT * (CC / 4);
        shift_gather_kernel<<<(total + 255) / 256, 256>>>(x, xs);
    }

    // 2) k, v, sr GEMMs (sigmoid fused into sr)
    {
        dim3 grid(CC / 128, MM / 128);
        gemm_tf32_kernel<0><<<grid, 256>>>(xs, kw, k);
        gemm_tf32_kernel<0><<<grid, 256>>>(xs, vw, v);
        gemm_tf32_kernel<1><<<grid, 256>>>(xs, rw, sr);
    }

    // 3) WKV pass 1 (t order) then pass 2 (zigzag-permuted order; the
    //    permutation is an involution so writes land directly in t-space)
    {
        dim3 gseg(LANES / 128, NSEG);
        int  gscan = LANES / 128;
        wkv_summary_kernel<0><<<gseg, 128>>>(k, v, sdec);
        wkv_scan_kernel<0><<<gscan, 128>>>(sdec);
        wkv_replay_kernel<0><<<gseg, 128>>>(k, v, sdec, sfst, v1);

        wkv_summary_kernel<1><<<gseg, 128>>>(k, v1, sdec);
        wkv_scan_kernel<1><<<gscan, 128>>>(sdec);
        wkv_replay_kernel<1><<<gseg, 128>>>(k, v1, sdec, sfst, vf);
    }

    // 4) out = (sr .* vf) @ ow^T  (product materialized into xs, then GEMM)
    {
        int total = ELEMS / 4;
        ewmul_kernel<<<(total + 255) / 256, 256>>>(sr, vf, xs);
        dim3 grid(CC / 128, MM / 128);
        gemm_tf32_kernel<0><<<grid, 256>>>(xs, ow, out);
    }
}

// round 6
// speedup vs baseline: 4.4211x; 3.2341x over previous
#include <cuda_runtime.h>
#include <cuda_bf16.h>
#include <cuda_fp16.h>
#include <mma.h>
#include <cstdint>

using namespace nvcuda;

// Problem constants (fixed by setup_inputs)
#define BB 8
#define HH 64
#define WW 64
#define TT 4096          // HH*WW
#define CC 768
#define MM (BB * TT)     // 32768
#define ELEMS (BB * TT * CC)
#define SEG 64
#define NSEG 64
#define LANES (BB * CC)  // 6144

// Shift table (24 groups of 32 channels)
__constant__ int c_dy[24] = {0, 0, 1, -1, 1, -1, 1, -1, 0, 0, 2, -2, 2, -2, 2, -2, 2, 1, 2, 1, -2, -1, -2, -1};
__constant__ int c_dx[24] = {1, -1, 0, 0, 1, -1, -1, 1, 2, -2, 0, 0, 2, -2, -2, 2, 1, 2, -1, -2, 1, 2, -1, -2};

// Scratch buffers (no cudaMalloc allowed)
__device__ __half g_xsh[ELEMS];
__device__ __half g_prod[ELEMS];
__device__ __half g_w[4][CC * CC];
__device__ float g_k[ELEMS];
__device__ float g_v[ELEMS];
__device__ float g_sr[ELEMS];
__device__ float g_v1[ELEMS];
__device__ float g_vf[ELEMS];
// WKV segment summaries + carry-in states
__device__ float g_sp[NSEG][LANES];
__device__ float g_sq[NSEG][LANES];
__device__ float g_so[NSEG][LANES];
__device__ float g_cp[NSEG][LANES];
__device__ float g_cq[NSEG][LANES];
__device__ float g_co[NSEG][LANES];

__device__ __forceinline__ int zig(int t) {
    int r = t >> 6, j = t & 63;
    return (r << 6) + ((r & 1) ? (63 - j) : j);
}

__device__ __forceinline__ void store_h4(__half* dst, float4 v) {
    __half2 a = __floats2half2_rn(v.x, v.y);
    __half2 b = __floats2half2_rn(v.z, v.w);
    *(uint2*)dst = make_uint2(*(unsigned*)&a, *(unsigned*)&b);
}

// ---------------------------------------------------------------------------
// 1) shift (mul_shift) + zigzag reorder + f32->f16 convert, fused gather.
// ---------------------------------------------------------------------------
__global__ void shift_gather_kernel(const float* __restrict__ x, __half* __restrict__ xs)
{
    int gid = blockIdx.x * blockDim.x + threadIdx.x;       // over B*T*(C/4)
    const int CV = CC / 4;
    if (gid >= BB * TT * CV) return;
    int cv = gid % CV;
    int bt = gid / CV;
    int t  = bt % TT;
    int b  = bt / TT;
    int c  = cv * 4;

    int r   = t >> 6;
    int j   = t & 63;
    int col = (r & 1) ? (63 - j) : j;                      // order[t] = (r, col)

    int g   = c >> 5;
    int srow = r - c_dy[g];
    int scol = col - c_dx[g];

    float4 val = make_float4(0.f, 0.f, 0.f, 0.f);
    if ((unsigned)srow < (unsigned)HH && (unsigned)scol < (unsigned)WW) {
        val = *(const float4*)&x[((size_t)b * TT + srow * WW + scol) * CC + c];
    }
    store_h4(&xs[((size_t)b * TT + t) * CC + c], val);
}

// ---------------------------------------------------------------------------
// weight convert: f32 -> f16
// ---------------------------------------------------------------------------
__global__ void wconv_kernel(const float* __restrict__ w, __half* __restrict__ wh, int n4)
{
    int gid = blockIdx.x * blockDim.x + threadIdx.x;
    if (gid >= n4) return;
    store_h4(&wh[(size_t)gid * 4], ((const float4*)w)[gid]);
}

// ---------------------------------------------------------------------------
// elementwise multiply + convert: (a .* b) -> f16
// ---------------------------------------------------------------------------
__global__ void ewmul_kernel(const float* __restrict__ a, const float* __restrict__ b,
                             __half* __restrict__ o)
{
    int gid = blockIdx.x * blockDim.x + threadIdx.x;
    if (gid >= ELEMS / 4) return;
    float4 va = ((const float4*)a)[gid];
    float4 vb = ((const float4*)b)[gid];
    va.x *= vb.x; va.y *= vb.y; va.z *= vb.z; va.w *= vb.w;
    store_h4(&o[(size_t)gid * 4], va);
}

// ---------------------------------------------------------------------------
// cp.async helpers
// ---------------------------------------------------------------------------
__device__ __forceinline__ void cp_async16(void* smem, const void* gmem) {
    unsigned int s = (unsigned int)__cvta_generic_to_shared(smem);
    asm volatile("cp.async.cg.shared.global [%0], [%1], 16;\n" :: "r"(s), "l"(gmem));
}
__device__ __forceinline__ void cp_commit() { asm volatile("cp.async.commit_group;\n" ::: "memory"); }
template<int N> __device__ __forceinline__ void cp_wait() { asm volatile("cp.async.wait_group %0;\n" :: "n"(N) : "memory"); }

// ---------------------------------------------------------------------------
// 2) fp16 tensor-core GEMM with cp.async double buffering.
//    C[m,n] = sum_k A[m,k] * W[n,k].  BM=128 BN=128 BK=32, 256 thr, 8 warps
//    (4x2), warp tile 32x64, fragments 16x16x16 half, f32 accumulate.
//    EPI: 0 none, 1 sigmoid.
// ---------------------------------------------------------------------------
template <int EPI>
__global__ __launch_bounds__(256)
void gemm_fp16_kernel(const __half* __restrict__ A, const __half* __restrict__ Wt,
                      float* __restrict__ Co)
{
    constexpr int BM = 128, BN = 128, BK = 32, PAD = 8;
    constexpr int LD = BK + PAD;                            // 40 halfs = 80B rows
    constexpr int K = CC, N = CC;

    __shared__ __half As[2][BM][LD];
    __shared__ __half Bs[2][BN][LD];

    const int m0 = blockIdx.y * BM;
    const int n0 = blockIdx.x * BN;
    const int tid = threadIdx.x;
    const int warp = tid >> 5;
    const int wm = warp >> 1;                               // 0..3 -> 32-row slab
    const int wn = warp & 1;                                // 0..1 -> 64-col slab

    wmma::fragment<wmma::accumulator, 16, 16, 16, float> cf[2][4];
#pragma unroll
    for (int i = 0; i < 2; i++)
#pragma unroll
        for (int jn = 0; jn < 4; jn++)
            wmma::fill_fragment(cf[i][jn], 0.f);

    // loader: A tile 128x32 halfs = 256 x 16B chunks; 1 per thread. B same.
    auto issue_loads = [&](int st, int k0) {
        int row = tid >> 1;                                 // 0..127
        int c8  = (tid & 1) * 8;                            // 0 or 8 (halfs)
        cp_async16(&As[st][row][c8], &A[(size_t)(m0 + row) * K + k0 + c8]);
        cp_async16(&Bs[st][row][c8], &Wt[(size_t)(n0 + row) * K + k0 + c8]);
        cp_async16(&As[st][row][c8 + 16], &A[(size_t)(m0 + row) * K + k0 + c8 + 16]);
        cp_async16(&Bs[st][row][c8 + 16], &Wt[(size_t)(n0 + row) * K + k0 + c8 + 16]);
    };

    // prologue: stage 0
    issue_loads(0, 0);
    cp_commit();

    int st = 0;
    for (int k0 = 0; k0 < K; k0 += BK, st ^= 1) {
        if (k0 + BK < K) issue_loads(st ^ 1, k0 + BK);
        cp_commit();
        cp_wait<1>();            // stage 'st' resident
        __syncthreads();

#pragma unroll
        for (int kk = 0; kk < BK; kk += 16) {
            wmma::fragment<wmma::matrix_a, 16, 16, 16, __half, wmma::row_major> af[2];
            wmma::fragment<wmma::matrix_b, 16, 16, 16, __half, wmma::col_major> bf[4];
#pragma unroll
            for (int i = 0; i < 2; i++)
                wmma::load_matrix_sync(af[i], &As[st][wm * 32 + i * 16][kk], LD);
#pragma unroll
            for (int jn = 0; jn < 4; jn++)
                wmma::load_matrix_sync(bf[jn], &Bs[st][wn * 64 + jn * 16][kk], LD);
#pragma unroll
            for (int i = 0; i < 2; i++)
#pragma unroll
                for (int jn = 0; jn < 4; jn++)
                    wmma::mma_sync(cf[i][jn], af[i], bf[jn], cf[i][jn]);
        }
        __syncthreads();         // protect stage about to be overwritten
    }

#pragma unroll
    for (int i = 0; i < 2; i++) {
#pragma unroll
        for (int jn = 0; jn < 4; jn++) {
            if (EPI == 1) {
#pragma unroll
                for (int e = 0; e < cf[i][jn].num_elements; e++)
                    cf[i][jn].x[e] = 1.f / (1.f + __expf(-cf[i][jn].x[e]));
            }
            wmma::store_matrix_sync(
                &Co[(size_t)(m0 + wm * 32 + i * 16) * N + n0 + wn * 64 + jn * 16],
                cf[i][jn], N, wmma::mem_row_major);
        }
    }
}

// ---------------------------------------------------------------------------
// 3) WKV, chunked parallel scan (unchanged from R4-passing version).
// ---------------------------------------------------------------------------
template <int PASS>
__global__ __launch_bounds__(128)
void wkv_summary_kernel(const float* __restrict__ kk, const float* __restrict__ vv,
                        const float* __restrict__ decay)
{
    int lane = blockIdx.x * 128 + threadIdx.x;              // 0..LANES-1
    int seg  = blockIdx.y;
    int b = lane / CC;
    int c = lane % CC;
    const float w = decay[PASS * CC + c] * (1.f / (float)TT);
    const size_t base = (size_t)b * TT * CC + c;

    float p = 0.f, q = 0.f, o = -1e38f;
#pragma unroll 8
    for (int t = 0; t < SEG; t++) {
        int tt = seg * SEG + t;
        int pidx = (PASS == 0) ? tt : zig(tt);
        size_t idx = base + (size_t)pidx * CC;
        float kt = kk[idx];
        float vt = vv[idx];
        float wo  = w + o;
        float no2 = fmaxf(wo, kt);
        float A2  = __expf(wo - no2);
        float B2  = __expf(kt - no2);
        p = A2 * p + B2 * vt;
        q = A2 * q + B2;
        o = no2;
    }
    g_sp[seg][lane] = p;
    g_sq[seg][lane] = q;
    g_so[seg][lane] = o;
}

template <int PASS>
__global__ __launch_bounds__(128)
void wkv_scan_kernel(const float* __restrict__ decay)
{
    int lane = blockIdx.x * 128 + threadIdx.x;
    if (lane >= LANES) return;
    int c = lane % CC;
    const float w  = decay[PASS * CC + c] * (1.f / (float)TT);
    const float wL = w * (float)SEG;

    float p = 0.f, q = 0.f, o = -1e38f;
#pragma unroll
    for (int seg = 0; seg < NSEG; seg++) {
        g_cp[seg][lane] = p;
        g_cq[seg][lane] = q;
        g_co[seg][lane] = o;
        float o1 = o + wL;
        float p2 = g_sp[seg][lane];
        float q2 = g_sq[seg][lane];
        float o2 = g_so[seg][lane];
        float no = fmaxf(o1, o2);
        float e1 = __expf(o1 - no);
        float e2 = __expf(o2 - no);
        p = e1 * p + e2 * p2;
        q = e1 * q + e2 * q2;
        o = no;
    }
}

template <int PASS>
__global__ __launch_bounds__(128)
void wkv_replay_kernel(const float* __restrict__ kk, const float* __restrict__ vv,
                       const float* __restrict__ decay, const float* __restrict__ first,
                       float* __restrict__ yo)
{
    int lane = blockIdx.x * 128 + threadIdx.x;
    int seg  = blockIdx.y;
    int b = lane / CC;
    int c = lane % CC;
    const float invT = 1.f / (float)TT;
    const float w = decay[PASS * CC + c] * invT;
    const float u = first[PASS * CC + c] * invT;
    const size_t base = (size_t)b * TT * CC + c;

    float p = g_cp[seg][lane];
    float q = g_cq[seg][lane];
    float o = g_co[seg][lane];

#pragma unroll 8
    for (int t = 0; t < SEG; t++) {
        int tt = seg * SEG + t;
        int pidx = (PASS == 0) ? tt : zig(tt);
        size_t idx = base + (size_t)pidx * CC;
        float kt = kk[idx];
        float vt = vv[idx];

        float uk = u + kt;
        float no = fmaxf(o, uk);
        float Ac = __expf(o - no);
        float Bc = __expf(uk - no);
        float y  = __fdividef(Ac * p + Bc * vt, Ac * q + Bc);
        yo[idx] = y;

        float wo  = w + o;
        float no2 = fmaxf(wo, kt);
        float A2  = __expf(wo - no2);
        float B2  = __expf(kt - no2);
        p = A2 * p + B2 * vt;
        q = A2 * q + B2;
        o = no2;
    }
}

// ---------------------------------------------------------------------------
// Launch
// ---------------------------------------------------------------------------
extern "C" void kernel_launch(void* const* d_in, const int* in_sizes, int n_in,
                              void* d_out, int out_size)
{
    const float* x    = (const float*)d_in[0];
    const float* kw   = (const float*)d_in[1];
    const float* vw   = (const float*)d_in[2];
    const float* rw   = (const float*)d_in[3];
    const float* ow   = (const float*)d_in[4];
    const float* sdec = (const float*)d_in[5];
    const float* sfst = (const float*)d_in[6];
    float* out        = (float*)d_out;

    __half *xs, *prod, *wh;
    float *k, *v, *sr, *v1, *vf;
    cudaGetSymbolAddress((void**)&xs,   g_xsh);
    cudaGetSymbolAddress((void**)&prod, g_prod);
    cudaGetSymbolAddress((void**)&wh,   g_w);
    cudaGetSymbolAddress((void**)&k,    g_k);
    cudaGetSymbolAddress((void**)&v,    g_v);
    cudaGetSymbolAddress((void**)&sr,   g_sr);
    cudaGetSymbolAddress((void**)&v1,   g_v1);
    cudaGetSymbolAddress((void**)&vf,   g_vf);

    // 1) shift + zigzag gather with fused f16 convert
    {
        int total = BB * TT * (CC / 4);
        shift_gather_kernel<<<(total + 255) / 256, 256>>>(x, xs);
    }
    // weight converts
    {
        int n4 = CC * CC / 4;
        int gr = (n4 + 255) / 256;
        wconv_kernel<<<gr, 256>>>(kw, wh + 0 * (size_t)CC * CC, n4);
        wconv_kernel<<<gr, 256>>>(vw, wh + 1 * (size_t)CC * CC, n4);
        wconv_kernel<<<gr, 256>>>(rw, wh + 2 * (size_t)CC * CC, n4);
        wconv_kernel<<<gr, 256>>>(ow, wh + 3 * (size_t)CC * CC, n4);
    }

    // 2) k, v, sr GEMMs (sigmoid fused into sr)
    {
        dim3 grid(CC / 128, MM / 128);
        gemm_fp16_kernel<0><<<grid, 256>>>(xs, wh + 0 * (size_t)CC * CC, k);
        gemm_fp16_kernel<0><<<grid, 256>>>(xs, wh + 1 * (size_t)CC * CC, v);
        gemm_fp16_kernel<1><<<grid, 256>>>(xs, wh + 2 * (size_t)CC * CC, sr);
    }

    // 3) WKV pass 1 (t order) then pass 2 (zigzag involution order)
    {
        dim3 gseg(LANES / 128, NSEG);
        int  gscan = LANES / 128;
        wkv_summary_kernel<0><<<gseg, 128>>>(k, v, sdec);
        wkv_scan_kernel<0><<<gscan, 128>>>(sdec);
        wkv_replay_kernel<0><<<gseg, 128>>>(k, v, sdec, sfst, v1);

        wkv_summary_kernel<1><<<gseg, 128>>>(k, v1, sdec);
        wkv_scan_kernel<1><<<gscan, 128>>>(sdec);
        wkv_replay_kernel<1><<<gseg, 128>>>(k, v1, sdec, sfst, vf);
    }

    // 4) out = (sr .* vf) @ ow^T  (product converted to f16, then GEMM)
    {
        int total = ELEMS / 4;
        ewmul_kernel<<<(total + 255) / 256, 256>>>(sr, vf, prod);
        dim3 grid(CC / 128, MM / 128);
        gemm_fp16_kernel<0><<<grid, 256>>>(prod, wh + 3 * (size_t)CC * CC, out);
    }
}